// round 9
// baseline (speedup 1.0000x reference)
#include <cuda_runtime.h>
#include <cstdint>

#define Bm 128
#define NAc 48
#define NBc 96
#define Hc 200
#define AFc 39
#define BFc 50      // ATOM_FDIM + BOND_FDIM
#define Lc 1000
#define Mrows (Bm * NBc)   // 12288
#define Marows (Bm * NAc)  // 6144
#define KAo 240            // padded 39+200+1

typedef unsigned long long u64;

// ---------------- f32x2 helpers (sm_103a FFMA2 via PTX) -------------------
__device__ __forceinline__ u64 pack2(float a, float b) {
    u64 r; asm("mov.b64 %0, {%1, %2};" : "=l"(r) : "f"(a), "f"(b)); return r;
}
__device__ __forceinline__ float2 unpack2(u64 a) {
    float2 v; asm("mov.b64 {%0, %1}, %2;" : "=f"(v.x), "=f"(v.y) : "l"(a)); return v;
}
__device__ __forceinline__ u64 ffma2(u64 a, u64 b, u64 c) {
    u64 d; asm("fma.rn.f32x2 %0, %1, %2, %3;" : "=l"(d) : "l"(a), "l"(b), "l"(c)); return d;
}

// ---------------- scratch (device globals; no allocation) ----------------
__device__ float g_binput[Mrows * Hc];
__device__ float g_message[Mrows * Hc];
__device__ float g_nei[Mrows * Hc];
__device__ float g_ain[Marows * KAo];
__device__ float g_wo[KAo * Hc];
__device__ float g_atomh[Marows * Hc];
__device__ float g_emb[Bm * Hc];
__device__ float g_prot[Bm * Hc];          // protein max-pool accum (relu >= 0)
__device__ float g_pv1[Bm * 96 * Lc];
__device__ float g_pv2[Bm * 128 * Lc];

// ---------------- init: zero the atomicMax accumulator -------------------
__global__ void k_zero_prot() {
    int i = blockIdx.x * blockDim.x + threadIdx.x;
    if (i < Bm * Hc) g_prot[i] = 0.f;
}

// ---------------- pad W_o (239 x 200) -> (240 x 200) ----------------------
__global__ void k_pad_w(const float* __restrict__ Wo) {
    int idx = blockIdx.x * 256 + threadIdx.x;
    if (idx >= KAo * Hc) return;
    int r = idx / Hc, h = idx - r * Hc;
    g_wo[idx] = (r < AFc + Hc) ? Wo[(size_t)r * Hc + h] : 0.f;
}

// ---------------- flat GEMM, m-paired FFMA2 -------------------------------
// Tile 256m x 64n, 256 threads (8 warps). Warp tn owns 8 n; lane tl owns
// 4 m-pairs strided 32 (mp = tl+32q -> m = 2mp, 2mp+1).
// MODE 0: Craw = A@Bw, Cout = relu(raw)    (binput)
// MODE 1: Cout = relu(Craw + A@Bw)          (message iter)
// MODE 2: Cout = relu(A@Bw + bias[n])       (atom output)
template <int KDIM, int KT, int MODE>
__global__ void __launch_bounds__(256) gemm_kernel(
        const float* __restrict__ A, const float* __restrict__ Bw,
        const float* __restrict__ bias,
        float* __restrict__ Craw, float* __restrict__ Cout) {
    __shared__ __align__(16) u64 sA2[KT * 129];   // row pad: 128 pairs + 1
    __shared__ __align__(16) u64 sW2[KT * 64];    // dup (w,w); 16B-aligned for LDS.128
    int m0 = blockIdx.x * 256, n0 = blockIdx.y * 64;
    int tid = threadIdx.x, tn = tid >> 5, tl = tid & 31;
    int nb = n0 + tn * 8;

    u64 acc[8][4];
    #pragma unroll
    for (int j = 0; j < 8; j++)
        #pragma unroll
        for (int q = 0; q < 4; q++) acc[j][q] = 0ull;

    for (int k0 = 0; k0 < KDIM; k0 += KT) {
        __syncthreads();
        for (int i = tid; i < 256 * KT; i += 256) {
            int m = i / KT, k = i - m * KT;
            ((float*)sA2)[k * 258 + m] = A[(size_t)(m0 + m) * KDIM + k0 + k];
        }
        for (int i = tid; i < KT * 64; i += 256) {
            int k = i >> 6, n = i & 63;
            float v = (n0 + n < Hc) ? Bw[(size_t)(k0 + k) * Hc + n0 + n] : 0.f;
            sW2[i] = pack2(v, v);
        }
        __syncthreads();
        #pragma unroll 1
        for (int k = 0; k < KT; k++) {
            const u64* ap = sA2 + k * 129 + tl;
            u64 a0 = ap[0], a1 = ap[32], a2 = ap[64], a3 = ap[96];
            const u64* wp = sW2 + k * 64 + tn * 8;
            u64 wv[8];
            #pragma unroll
            for (int j2 = 0; j2 < 4; j2++) {
                longlong2 t2 = *(const longlong2*)(wp + 2 * j2);
                wv[2 * j2] = (u64)t2.x; wv[2 * j2 + 1] = (u64)t2.y;
            }
            #pragma unroll
            for (int j = 0; j < 8; j++) {
                acc[j][0] = ffma2(wv[j], a0, acc[j][0]);
                acc[j][1] = ffma2(wv[j], a1, acc[j][1]);
                acc[j][2] = ffma2(wv[j], a2, acc[j][2]);
                acc[j][3] = ffma2(wv[j], a3, acc[j][3]);
            }
        }
    }

    if (nb >= Hc) return;   // Hc % 8 == 0: octets all-or-nothing
    float bj[8];
    if (MODE == 2) {
        #pragma unroll
        for (int j = 0; j < 8; j++) bj[j] = bias[nb + j];
    }
    #pragma unroll
    for (int q = 0; q < 4; q++) {
        int mp = tl + 32 * q;
        #pragma unroll
        for (int h = 0; h < 2; h++) {
            int m = m0 + 2 * mp + h;
            float c8[8];
            #pragma unroll
            for (int j = 0; j < 8; j++) {
                float2 v = unpack2(acc[j][q]);
                c8[j] = h ? v.y : v.x;
            }
            size_t base = (size_t)m * Hc + nb;
            if (MODE == 2) {
                #pragma unroll
                for (int j = 0; j < 8; j++) c8[j] += bj[j];
            }
            if (MODE == 1) {
                float4 r0 = *(const float4*)(Craw + base);
                float4 r1 = *(const float4*)(Craw + base + 4);
                c8[0] += r0.x; c8[1] += r0.y; c8[2] += r0.z; c8[3] += r0.w;
                c8[4] += r1.x; c8[5] += r1.y; c8[6] += r1.z; c8[7] += r1.w;
            }
            if (MODE == 0) {
                *(float4*)(Craw + base) = make_float4(c8[0], c8[1], c8[2], c8[3]);
                *(float4*)(Craw + base + 4) = make_float4(c8[4], c8[5], c8[6], c8[7]);
            }
            #pragma unroll
            for (int j = 0; j < 8; j++) c8[j] = fmaxf(c8[j], 0.f);
            *(float4*)(Cout + base) = make_float4(c8[0], c8[1], c8[2], c8[3]);
            *(float4*)(Cout + base + 4) = make_float4(c8[4], c8[5], c8[6], c8[7]);
        }
    }
}

// ---------------- neighbor gather: nei = sum_j message[bg[j]] -------------
__global__ void k_gather(const int* __restrict__ bgraph) {
    int idx = blockIdx.x * 256 + threadIdx.x;
    if (idx >= Mrows * Hc) return;
    int m = idx / Hc, h = idx - m * Hc;
    int b = m / NBc;
    const int* bg = bgraph + m * 6;
    const float* msgB = g_message + (size_t)b * NBc * Hc + h;
    float s = 0.f;
    #pragma unroll
    for (int j = 0; j < 6; j++) s += msgB[bg[j] * Hc];
    g_nei[idx] = s;
}

// ---------------- atom input build: [fa | gather(message) | 0] ------------
__global__ void k_gather_atoms(const int* __restrict__ agraph, const float* __restrict__ fa) {
    int idx = blockIdx.x * 256 + threadIdx.x;
    if (idx >= Marows * KAo) return;
    int m = idx / KAo, c = idx - m * KAo;
    int b = m / NAc;
    float v = 0.f;
    if (c < AFc) {
        v = fa[(size_t)m * AFc + c];
    } else if (c < AFc + Hc) {
        int h = c - AFc;
        const int* ag = agraph + m * 6;
        const float* msgB = g_message + (size_t)b * NBc * Hc + h;
        #pragma unroll
        for (int j = 0; j < 6; j++) v += msgB[ag[j] * Hc];
    }
    g_ain[idx] = v;
}

// ---------------- mean over atoms -> molecule embedding -------------------
__global__ void k_mean() {
    int b = blockIdx.x, h = threadIdx.x;
    if (h >= Hc) return;
    const float* ah = g_atomh + (size_t)b * NAc * Hc + h;
    float s = 0.f;
    for (int na = 0; na < NAc; na++) s += ah[(size_t)na * Hc];
    g_emb[b * Hc + h] = s * (1.f / NAc);
}

// ---------------- conv1d + relu (+fused max), l-adjacent FFMA2 ------------
// Block tile: CoT co x 256 l, 256 threads (8 warps). Warp wid owns CPW=CoT/8
// co; lane tl owns 8 adjacent l (4 pairs).
// sE[p]=(x0,x1) even pairs; sO[p]=(x1,x2) odd-shifted pairs, BOTH written at
// tile-load time (values already in regs) -> zero repack ALU in inner loop.
// Weights in [(ci*K+t)*8 + wid]*WPAD layout (WPAD even) -> 16B-aligned
// LDS.128 vector loads.
template <int CIN, int COUT, int K, int CI_TILE, int CoT, bool MAXPOOL, bool EMBED>
__global__ void __launch_bounds__(256, 3) conv_kernel(
        const float* __restrict__ in, const int* __restrict__ seq,
        const float* __restrict__ Ep,
        const float* __restrict__ w, const float* __restrict__ bias,
        float* __restrict__ out, float* __restrict__ pmax) {
    constexpr int TL = 256, PAD = K / 2, CPW = CoT / 8;
    constexpr int WPAD = CPW + (CPW & 1);          // even stride for LDS.128
    constexpr int NE = PAD + 4;                    // eE entries actually used
    extern __shared__ char smraw[];
    u64* sE = (u64*)smraw;                     // CI_TILE * 256
    u64* sO = sE + CI_TILE * 256;              // CI_TILE * 256
    u64* sW2 = sO + CI_TILE * 256;             // CI_TILE * K * 8 * WPAD
    int b = blockIdx.z, coBase = blockIdx.y * CoT, lBase = blockIdx.x * TL;
    int tid = threadIdx.x, wid = tid >> 5, tl = tid & 31;
    int co0 = wid * CPW;

    u64 acc[CPW][4];
    #pragma unroll
    for (int c = 0; c < CPW; c++) {
        float bv = bias[coBase + co0 + c];
        u64 bp = pack2(bv, bv);
        #pragma unroll
        for (int u = 0; u < 4; u++) acc[c][u] = bp;
    }

    const float* inB = EMBED ? nullptr : in + (size_t)b * CIN * Lc;
    const int* seqB = EMBED ? seq + (size_t)b * Lc : nullptr;

    for (int ct = 0; ct < CIN; ct += CI_TILE) {
        __syncthreads();
        for (int i = tid; i < CI_TILE * 256; i += 256) {
            int ci = i >> 8, r = i & 255, j = r >> 5, lt = r & 31;
            int gl = lBase - PAD + 8 * lt + 2 * j;
            float v0 = 0.f, v1 = 0.f, v2 = 0.f;
            if (EMBED) {
                if (gl >= 0 && gl < Lc) v0 = Ep[seqB[gl] * 50 + ct + ci];
                if (gl + 1 >= 0 && gl + 1 < Lc) v1 = Ep[seqB[gl + 1] * 50 + ct + ci];
                if (gl + 2 >= 0 && gl + 2 < Lc) v2 = Ep[seqB[gl + 2] * 50 + ct + ci];
            } else {
                const float* row = inB + (size_t)(ct + ci) * Lc;
                if (gl >= 0 && gl < Lc) v0 = row[gl];
                if (gl + 1 >= 0 && gl + 1 < Lc) v1 = row[gl + 1];
                if (gl + 2 >= 0 && gl + 2 < Lc) v2 = row[gl + 2];
            }
            sE[i] = pack2(v0, v1);
            sO[i] = pack2(v1, v2);
        }
        for (int i = tid; i < CI_TILE * K * CoT; i += 256) {
            int q = i / CoT;                 // ci*K + t
            int c40 = i - q * CoT;
            int w8 = c40 / CPW, c = c40 - w8 * CPW;
            int ci = q / K, t = q - ci * K;
            float val = w[((size_t)(coBase + c40) * CIN + ct + ci) * K + t];
            sW2[(q * 8 + w8) * WPAD + c] = pack2(val, val);
        }
        __syncthreads();
        #pragma unroll 1
        for (int ci = 0; ci < CI_TILE; ci++) {
            u64 eE[NE];
            const u64* ep = sE + ci * 256 + tl;
            #pragma unroll
            for (int j = 0; j < NE; j++) eE[j] = ep[j * 32];
            const u64* opb = sO + ci * 256 + tl;
            const u64* wb = sW2 + (size_t)(ci * K) * (8 * WPAD) + wid * WPAD;
            #pragma unroll
            for (int t = 0; t < K; t++) {
                const u64* wp = wb + t * (8 * WPAD);
                u64 wv[CPW];
                #pragma unroll
                for (int c2 = 0; c2 < CPW / 2; c2++) {
                    longlong2 t2 = *(const longlong2*)(wp + 2 * c2);
                    wv[2 * c2] = (u64)t2.x; wv[2 * c2 + 1] = (u64)t2.y;
                }
                if (CPW & 1) wv[CPW - 1] = wp[CPW - 1];
                int s = t >> 1;
                #pragma unroll
                for (int u = 0; u < 4; u++) {
                    u64 x = (t & 1) ? opb[(s + u) * 32] : eE[s + u];
                    #pragma unroll
                    for (int c = 0; c < CPW; c++)
                        acc[c][u] = ffma2(wv[c], x, acc[c][u]);
                }
            }
        }
    }

    int lThread = lBase + 8 * tl;
    if (MAXPOOL) {
        float mx[CPW];
        #pragma unroll
        for (int c = 0; c < CPW; c++) {
            float m = 0.f;
            if (lThread < Lc) {
                #pragma unroll
                for (int u = 0; u < 4; u++) {
                    float2 v = unpack2(acc[c][u]);
                    m = fmaxf(m, fmaxf(v.x, v.y));
                }
            }
            mx[c] = m;   // relu folded (>= 0)
        }
        #pragma unroll
        for (int off = 16; off; off >>= 1)
            #pragma unroll
            for (int c = 0; c < CPW; c++)
                mx[c] = fmaxf(mx[c], __shfl_xor_sync(0xffffffffu, mx[c], off));
        if (tl == 0) {
            #pragma unroll
            for (int c = 0; c < CPW; c++)
                atomicMax((int*)(pmax + b * COUT + coBase + co0 + c), __float_as_int(mx[c]));
        }
    } else {
        if (lThread < Lc) {   // Lc % 8 == 0: 8-l chunks all-or-nothing
            float* outB = out + (size_t)b * COUT * Lc;
            #pragma unroll
            for (int c = 0; c < CPW; c++) {
                float2 p0 = unpack2(acc[c][0]), p1 = unpack2(acc[c][1]);
                float2 p2 = unpack2(acc[c][2]), p3 = unpack2(acc[c][3]);
                float* orow = outB + (size_t)(coBase + co0 + c) * Lc + lThread;
                *(float4*)orow = make_float4(fmaxf(p0.x, 0.f), fmaxf(p0.y, 0.f),
                                             fmaxf(p1.x, 0.f), fmaxf(p1.y, 0.f));
                *(float4*)(orow + 4) = make_float4(fmaxf(p2.x, 0.f), fmaxf(p2.y, 0.f),
                                                   fmaxf(p3.x, 0.f), fmaxf(p3.y, 0.f));
            }
        }
    }
}

// ---------------- FC head: 400 -> 200 -> 100 -> 1 ------------------------
__global__ void k_fc(const float* __restrict__ w0, const float* __restrict__ b0,
                     const float* __restrict__ w1, const float* __restrict__ b1,
                     const float* __restrict__ w2, const float* __restrict__ b2,
                     float* __restrict__ out) {
    __shared__ float sx[400];
    __shared__ float sy0[200];
    __shared__ float sy1[100];
    int b = blockIdx.x, tid = threadIdx.x;
    for (int k = tid; k < 400; k += blockDim.x)
        sx[k] = (k < 200) ? g_emb[b * 200 + k] : g_prot[b * 200 + (k - 200)];
    __syncthreads();
    for (int j = tid; j < 200; j += blockDim.x) {
        float a = b0[j];
        for (int k = 0; k < 400; k++) a += sx[k] * w0[k * 200 + j];
        sy0[j] = fmaxf(a, 0.f);
    }
    __syncthreads();
    for (int j = tid; j < 100; j += blockDim.x) {
        float a = b1[j];
        for (int k = 0; k < 200; k++) a += sy0[k] * w1[k * 100 + j];
        sy1[j] = fmaxf(a, 0.f);
    }
    __syncthreads();
    if (tid == 0) {
        float a = b2[0];
        for (int k = 0; k < 100; k++) a += sy1[k] * w2[k];
        out[b] = a;
    }
}

// ---------------- launch --------------------------------------------------
extern "C" void kernel_launch(void* const* d_in, const int* in_sizes, int n_in,
                              void* d_out, int out_size) {
    const float* fatoms = (const float*)d_in[0];
    const float* fbonds = (const float*)d_in[1];
    const int* agraph = (const int*)d_in[2];
    const int* bgraph = (const int*)d_in[3];
    const int* pseq = (const int*)d_in[4];
    const float* W_i = (const float*)d_in[5];
    const float* W_h = (const float*)d_in[6];
    const float* W_o_w = (const float*)d_in[7];
    const float* W_o_b = (const float*)d_in[8];
    const float* Ep = (const float*)d_in[9];
    const float* c0w = (const float*)d_in[10];
    const float* c0b = (const float*)d_in[11];
    const float* c1w = (const float*)d_in[12];
    const float* c1b = (const float*)d_in[13];
    const float* c2w = (const float*)d_in[14];
    const float* c2b = (const float*)d_in[15];
    const float* f0w = (const float*)d_in[16];
    const float* f0b = (const float*)d_in[17];
    const float* f1w = (const float*)d_in[18];
    const float* f1b = (const float*)d_in[19];
    const float* f2w = (const float*)d_in[20];
    const float* f2b = (const float*)d_in[21];
    float* out = (float*)d_out;

    // conv dynamic smem: (2*CI_TILE*256 + CI_TILE*K*8*WPAD) * 8
    const int smem_c0 = (2 * 10 * 256 + 10 * 3 * 8 * 4) * 8;   // 48640
    const int smem_c1 = (2 * 8 * 256 + 8 * 5 * 8 * 4) * 8;     // 43008
    const int smem_c2 = (2 * 8 * 256 + 8 * 7 * 8 * 6) * 8;     // 54272

    // Resolve REAL device addresses of __device__ globals passed as args.
    static float *p_pv1 = nullptr, *p_pv2 = nullptr, *p_prot = nullptr,
                 *p_nei = nullptr, *p_binput = nullptr, *p_message = nullptr,
                 *p_ain = nullptr, *p_wo = nullptr, *p_atomh = nullptr;
    static bool init_done = false;
    if (!init_done) {
        cudaGetSymbolAddress((void**)&p_pv1, g_pv1);
        cudaGetSymbolAddress((void**)&p_pv2, g_pv2);
        cudaGetSymbolAddress((void**)&p_prot, g_prot);
        cudaGetSymbolAddress((void**)&p_nei, g_nei);
        cudaGetSymbolAddress((void**)&p_binput, g_binput);
        cudaGetSymbolAddress((void**)&p_message, g_message);
        cudaGetSymbolAddress((void**)&p_ain, g_ain);
        cudaGetSymbolAddress((void**)&p_wo, g_wo);
        cudaGetSymbolAddress((void**)&p_atomh, g_atomh);
        cudaFuncSetAttribute((const void*)conv_kernel<50, 96, 3, 10, 32, false, true>,
                             cudaFuncAttributeMaxDynamicSharedMemorySize, smem_c0);
        cudaFuncSetAttribute((const void*)conv_kernel<96, 128, 5, 8, 32, false, false>,
                             cudaFuncAttributeMaxDynamicSharedMemorySize, smem_c1);
        cudaFuncSetAttribute((const void*)conv_kernel<128, 200, 7, 8, 40, true, false>,
                             cudaFuncAttributeMaxDynamicSharedMemorySize, smem_c2);
        init_done = true;
    }

    // Conv chain launched first so the profiled slot (index 3) is conv2.
    k_zero_prot<<<(Bm * Hc + 255) / 256, 256>>>();                       // 0
    {
        dim3 g(4, 3, Bm);   // 96 = 3 x 32
        conv_kernel<50, 96, 3, 10, 32, false, true><<<g, 256, smem_c0>>>(
            nullptr, pseq, Ep, c0w, c0b, p_pv1, nullptr);                // 1
    }
    {
        dim3 g(4, 4, Bm);   // 128 = 4 x 32
        conv_kernel<96, 128, 5, 8, 32, false, false><<<g, 256, smem_c1>>>(
            p_pv1, nullptr, nullptr, c1w, c1b, p_pv2, nullptr);          // 2
    }
    {
        dim3 g(4, 5, Bm);   // 200 = 5 x 40
        conv_kernel<128, 200, 7, 8, 40, true, false><<<g, 256, smem_c2>>>(
            p_pv2, nullptr, nullptr, c2w, c2b, nullptr, p_prot);         // 3
    }
    k_pad_w<<<(KAo * Hc + 255) / 256, 256>>>(W_o_w);                     // 4
    {
        dim3 g(Mrows / 256, 4);
        int gg = (Mrows * Hc + 255) / 256;
        gemm_kernel<50, 25, 0><<<g, 256>>>(fbonds, W_i, nullptr, p_binput, p_message);  // 5
        k_gather<<<gg, 256>>>(bgraph);                                   // 6
        gemm_kernel<200, 25, 1><<<g, 256>>>(p_nei, W_h, nullptr, p_binput, p_message);  // 7
        k_gather<<<gg, 256>>>(bgraph);                                   // 8
        gemm_kernel<200, 25, 1><<<g, 256>>>(p_nei, W_h, nullptr, p_binput, p_message);  // 9
    }
    k_gather_atoms<<<(Marows * KAo + 255) / 256, 256>>>(agraph, fatoms); // 10
    {
        dim3 g(Marows / 256, 4);
        gemm_kernel<KAo, 24, 2><<<g, 256>>>(p_ain, p_wo, W_o_b, nullptr, p_atomh);      // 11
    }
    k_mean<<<Bm, 224>>>();                                               // 12
    k_fc<<<Bm, 256>>>(f0w, f0b, f1w, f1b, f2w, f2b, out);                // 13
}

// round 12
// speedup vs baseline: 1.1674x; 1.1674x over previous
#include <cuda_runtime.h>
#include <cstdint>

#define Bm 128
#define NAc 48
#define NBc 96
#define Hc 200
#define AFc 39
#define BFc 50      // ATOM_FDIM + BOND_FDIM
#define Lc 1000
#define Mrows (Bm * NBc)   // 12288
#define Marows (Bm * NAc)  // 6144
#define KAo 240            // padded 39+200+1

typedef unsigned long long u64;

// ---------------- f32x2 helpers (sm_103a FFMA2 via PTX) -------------------
__device__ __forceinline__ u64 pack2(float a, float b) {
    u64 r; asm("mov.b64 %0, {%1, %2};" : "=l"(r) : "f"(a), "f"(b)); return r;
}
__device__ __forceinline__ float2 unpack2(u64 a) {
    float2 v; asm("mov.b64 {%0, %1}, %2;" : "=f"(v.x), "=f"(v.y) : "l"(a)); return v;
}
__device__ __forceinline__ u64 ffma2(u64 a, u64 b, u64 c) {
    u64 d; asm("fma.rn.f32x2 %0, %1, %2, %3;" : "=l"(d) : "l"(a), "l"(b), "l"(c)); return d;
}

// ---------------- scratch (device globals; no allocation) ----------------
__device__ float g_binput[Mrows * Hc];
__device__ float g_message[Mrows * Hc];
__device__ float g_nei[Mrows * Hc];
__device__ float g_ain[Marows * KAo];
__device__ float g_wo[KAo * Hc];
__device__ float g_atomh[Marows * Hc];
__device__ float g_emb[Bm * Hc];
__device__ float g_prot[Bm * Hc];          // protein max-pool accum (relu >= 0)
__device__ float g_pv1[Bm * 96 * Lc];
__device__ float g_pv2[Bm * 128 * Lc];

// ---------------- init: zero the atomicMax accumulator -------------------
__global__ void k_zero_prot() {
    int i = blockIdx.x * blockDim.x + threadIdx.x;
    if (i < Bm * Hc) g_prot[i] = 0.f;
}

// ---------------- pad W_o (239 x 200) -> (240 x 200) ----------------------
__global__ void k_pad_w(const float* __restrict__ Wo) {
    int idx = blockIdx.x * 256 + threadIdx.x;
    if (idx >= KAo * Hc) return;
    int r = idx / Hc, h = idx - r * Hc;
    g_wo[idx] = (r < AFc + Hc) ? Wo[(size_t)r * Hc + h] : 0.f;
}

// ---------------- flat GEMM, m-paired FFMA2 -------------------------------
// Tile 256m x 64n, 256 threads (8 warps). Warp tn owns 8 n; lane tl owns
// 4 m-pairs strided 32 (mp = tl+32q -> m = 2mp, 2mp+1).
// MODE 0: Craw = A@Bw, Cout = relu(raw)    (binput)
// MODE 1: Cout = relu(Craw + A@Bw)          (message iter)
// MODE 2: Cout = relu(A@Bw + bias[n])       (atom output)
template <int KDIM, int KT, int MODE>
__global__ void __launch_bounds__(256) gemm_kernel(
        const float* __restrict__ A, const float* __restrict__ Bw,
        const float* __restrict__ bias,
        float* __restrict__ Craw, float* __restrict__ Cout) {
    __shared__ __align__(16) u64 sA2[KT * 129];   // row pad: 128 pairs + 1
    __shared__ __align__(16) u64 sW2[KT * 64];    // dup (w,w); 16B-aligned for LDS.128
    int m0 = blockIdx.x * 256, n0 = blockIdx.y * 64;
    int tid = threadIdx.x, tn = tid >> 5, tl = tid & 31;
    int nb = n0 + tn * 8;

    u64 acc[8][4];
    #pragma unroll
    for (int j = 0; j < 8; j++)
        #pragma unroll
        for (int q = 0; q < 4; q++) acc[j][q] = 0ull;

    for (int k0 = 0; k0 < KDIM; k0 += KT) {
        __syncthreads();
        for (int i = tid; i < 256 * KT; i += 256) {
            int m = i / KT, k = i - m * KT;
            ((float*)sA2)[k * 258 + m] = A[(size_t)(m0 + m) * KDIM + k0 + k];
        }
        for (int i = tid; i < KT * 64; i += 256) {
            int k = i >> 6, n = i & 63;
            float v = (n0 + n < Hc) ? Bw[(size_t)(k0 + k) * Hc + n0 + n] : 0.f;
            sW2[i] = pack2(v, v);
        }
        __syncthreads();
        #pragma unroll 1
        for (int k = 0; k < KT; k++) {
            const u64* ap = sA2 + k * 129 + tl;
            u64 a0 = ap[0], a1 = ap[32], a2 = ap[64], a3 = ap[96];
            const u64* wp = sW2 + k * 64 + tn * 8;
            u64 wv[8];
            #pragma unroll
            for (int j2 = 0; j2 < 4; j2++) {
                longlong2 t2 = *(const longlong2*)(wp + 2 * j2);
                wv[2 * j2] = (u64)t2.x; wv[2 * j2 + 1] = (u64)t2.y;
            }
            #pragma unroll
            for (int j = 0; j < 8; j++) {
                acc[j][0] = ffma2(wv[j], a0, acc[j][0]);
                acc[j][1] = ffma2(wv[j], a1, acc[j][1]);
                acc[j][2] = ffma2(wv[j], a2, acc[j][2]);
                acc[j][3] = ffma2(wv[j], a3, acc[j][3]);
            }
        }
    }

    if (nb >= Hc) return;   // Hc % 8 == 0: octets all-or-nothing
    float bj[8];
    if (MODE == 2) {
        #pragma unroll
        for (int j = 0; j < 8; j++) bj[j] = bias[nb + j];
    }
    #pragma unroll
    for (int q = 0; q < 4; q++) {
        int mp = tl + 32 * q;
        #pragma unroll
        for (int h = 0; h < 2; h++) {
            int m = m0 + 2 * mp + h;
            float c8[8];
            #pragma unroll
            for (int j = 0; j < 8; j++) {
                float2 v = unpack2(acc[j][q]);
                c8[j] = h ? v.y : v.x;
            }
            size_t base = (size_t)m * Hc + nb;
            if (MODE == 2) {
                #pragma unroll
                for (int j = 0; j < 8; j++) c8[j] += bj[j];
            }
            if (MODE == 1) {
                float4 r0 = *(const float4*)(Craw + base);
                float4 r1 = *(const float4*)(Craw + base + 4);
                c8[0] += r0.x; c8[1] += r0.y; c8[2] += r0.z; c8[3] += r0.w;
                c8[4] += r1.x; c8[5] += r1.y; c8[6] += r1.z; c8[7] += r1.w;
            }
            if (MODE == 0) {
                *(float4*)(Craw + base) = make_float4(c8[0], c8[1], c8[2], c8[3]);
                *(float4*)(Craw + base + 4) = make_float4(c8[4], c8[5], c8[6], c8[7]);
            }
            #pragma unroll
            for (int j = 0; j < 8; j++) c8[j] = fmaxf(c8[j], 0.f);
            *(float4*)(Cout + base) = make_float4(c8[0], c8[1], c8[2], c8[3]);
            *(float4*)(Cout + base + 4) = make_float4(c8[4], c8[5], c8[6], c8[7]);
        }
    }
}

// ---------------- neighbor gather: nei = sum_j message[bg[j]] -------------
__global__ void k_gather(const int* __restrict__ bgraph) {
    int idx = blockIdx.x * 256 + threadIdx.x;
    if (idx >= Mrows * Hc) return;
    int m = idx / Hc, h = idx - m * Hc;
    int b = m / NBc;
    const int* bg = bgraph + m * 6;
    const float* msgB = g_message + (size_t)b * NBc * Hc + h;
    float s = 0.f;
    #pragma unroll
    for (int j = 0; j < 6; j++) s += msgB[bg[j] * Hc];
    g_nei[idx] = s;
}

// ---------------- atom input build: [fa | gather(message) | 0] ------------
__global__ void k_gather_atoms(const int* __restrict__ agraph, const float* __restrict__ fa) {
    int idx = blockIdx.x * 256 + threadIdx.x;
    if (idx >= Marows * KAo) return;
    int m = idx / KAo, c = idx - m * KAo;
    int b = m / NAc;
    float v = 0.f;
    if (c < AFc) {
        v = fa[(size_t)m * AFc + c];
    } else if (c < AFc + Hc) {
        int h = c - AFc;
        const int* ag = agraph + m * 6;
        const float* msgB = g_message + (size_t)b * NBc * Hc + h;
        #pragma unroll
        for (int j = 0; j < 6; j++) v += msgB[ag[j] * Hc];
    }
    g_ain[idx] = v;
}

// ---------------- mean over atoms -> molecule embedding -------------------
__global__ void k_mean() {
    int b = blockIdx.x, h = threadIdx.x;
    if (h >= Hc) return;
    const float* ah = g_atomh + (size_t)b * NAc * Hc + h;
    float s = 0.f;
    for (int na = 0; na < NAc; na++) s += ah[(size_t)na * Hc];
    g_emb[b * Hc + h] = s * (1.f / NAc);
}

// ---------------- conv1d + relu (+fused max) — ROUND-5 design -------------
// Block tile: CoT co x 256 l. Threads NT = (CoT/8)*32: warp tco covers 8 co,
// lane tl covers l-pairs at l = 2*(tl + 32u), u=0..3.
// smem: sInE[p]=(x[2p],x[2p+1]), sInO[p]=(x[2p+1],x[2p+2]) (even/odd shifted
// copies -> every tap t is one aligned LDS.64); sW2 = (w,w) broadcast.
// 32 independent FFMA2 per (ci,t) per thread.
// EMBED: input synthesized from Ep[seq[l]] (fuses the embedding gather).
template <int CIN, int COUT, int K, int CI_TILE, int CoT, int NT, bool MAXPOOL, bool EMBED>
__global__ void __launch_bounds__(NT) conv_kernel(
        const float* __restrict__ in, const int* __restrict__ seq,
        const float* __restrict__ Ep,
        const float* __restrict__ w, const float* __restrict__ bias,
        float* __restrict__ out, float* __restrict__ pmax) {
    constexpr int TL = 256, PAD = K / 2, NP = (TL + K - 1) / 2 + 2;
    extern __shared__ char smraw[];
    u64* sInE = (u64*)smraw;                   // CI_TILE*NP
    u64* sInO = sInE + CI_TILE * NP;           // CI_TILE*NP
    u64* sW2 = sInO + CI_TILE * NP;            // CI_TILE*K*CoT
    int b = blockIdx.z, coBase = blockIdx.y * CoT, lBase = blockIdx.x * TL;
    int tid = threadIdx.x, tco = tid >> 5, tl = tid & 31;
    int co0 = tco * 8;

    u64 acc[8][4];
    #pragma unroll
    for (int i = 0; i < 8; i++) {
        float bv = bias[coBase + co0 + i];
        u64 bp = pack2(bv, bv);
        #pragma unroll
        for (int j = 0; j < 4; j++) acc[i][j] = bp;
    }

    const float* inB = EMBED ? nullptr : in + (size_t)b * CIN * Lc;
    const int* seqB = EMBED ? seq + (size_t)b * Lc : nullptr;

    for (int ct = 0; ct < CIN; ct += CI_TILE) {
        __syncthreads();
        for (int i = tid; i < CI_TILE * NP; i += NT) {
            int ci = i / NP, p = i - ci * NP;
            int gl = lBase - PAD + 2 * p;
            float v0 = 0.f, v1 = 0.f, v2 = 0.f;
            if (EMBED) {
                if (gl >= 0 && gl < Lc) v0 = Ep[seqB[gl] * 50 + ct + ci];
                if (gl + 1 >= 0 && gl + 1 < Lc) v1 = Ep[seqB[gl + 1] * 50 + ct + ci];
                if (gl + 2 >= 0 && gl + 2 < Lc) v2 = Ep[seqB[gl + 2] * 50 + ct + ci];
            } else {
                const float* row = inB + (size_t)(ct + ci) * Lc;
                if (gl >= 0 && gl < Lc) v0 = row[gl];
                if (gl + 1 >= 0 && gl + 1 < Lc) v1 = row[gl + 1];
                if (gl + 2 >= 0 && gl + 2 < Lc) v2 = row[gl + 2];
            }
            sInE[i] = pack2(v0, v1);
            sInO[i] = pack2(v1, v2);
        }
        for (int i = tid; i < CI_TILE * K * CoT; i += NT) {
            int co = i % CoT; int r = i / CoT; int t = r % K; int ci = r / K;
            float wv = w[((size_t)(coBase + co) * CIN + ct + ci) * K + t];
            sW2[i] = pack2(wv, wv);
        }
        __syncthreads();
        #pragma unroll 1
        for (int ci = 0; ci < CI_TILE; ci++) {
            const u64* rE = sInE + ci * NP + tl;
            const u64* rO = sInO + ci * NP + tl;
            const u64* wr = sW2 + (size_t)(ci * K) * CoT + co0;
            #pragma unroll
            for (int t = 0; t < K; t++) {
                const u64* xr = ((t & 1) ? rO : rE) + (t >> 1);
                u64 x0 = xr[0], x1 = xr[32], x2 = xr[64], x3 = xr[96];
                const u64* wp = wr + t * CoT;
                u64 wv[8];
                #pragma unroll
                for (int c2 = 0; c2 < 4; c2++) {
                    longlong2 t2 = *(const longlong2*)(wp + 2 * c2);
                    wv[2 * c2] = (u64)t2.x; wv[2 * c2 + 1] = (u64)t2.y;
                }
                #pragma unroll
                for (int i = 0; i < 8; i++) {
                    acc[i][0] = ffma2(wv[i], x0, acc[i][0]);
                    acc[i][1] = ffma2(wv[i], x1, acc[i][1]);
                    acc[i][2] = ffma2(wv[i], x2, acc[i][2]);
                    acc[i][3] = ffma2(wv[i], x3, acc[i][3]);
                }
            }
        }
    }

    if (MAXPOOL) {
        float mx[8];
        #pragma unroll
        for (int i = 0; i < 8; i++) {
            float m = 0.f;
            #pragma unroll
            for (int j = 0; j < 4; j++) {
                int l = lBase + 2 * (tl + 32 * j);
                if (l < Lc) {
                    float2 v = unpack2(acc[i][j]);
                    m = fmaxf(m, fmaxf(v.x, v.y));
                }
            }
            mx[i] = m;   // relu folded: m >= 0
        }
        #pragma unroll
        for (int off = 16; off; off >>= 1)
            #pragma unroll
            for (int i = 0; i < 8; i++)
                mx[i] = fmaxf(mx[i], __shfl_xor_sync(0xffffffffu, mx[i], off));
        if (tl == 0) {
            #pragma unroll
            for (int i = 0; i < 8; i++)
                atomicMax((int*)(pmax + b * COUT + coBase + co0 + i), __float_as_int(mx[i]));
        }
    } else {
        float* outB = out + (size_t)b * COUT * Lc;
        #pragma unroll
        for (int i = 0; i < 8; i++) {
            float* orow = outB + (size_t)(coBase + co0 + i) * Lc;
            #pragma unroll
            for (int j = 0; j < 4; j++) {
                int l = lBase + 2 * (tl + 32 * j);
                if (l < Lc) {   // Lc even: pair fully valid
                    float2 v = unpack2(acc[i][j]);
                    *(u64*)(orow + l) = pack2(fmaxf(v.x, 0.f), fmaxf(v.y, 0.f));
                }
            }
        }
    }
}

// ---------------- FC head: 400 -> 200 -> 100 -> 1 ------------------------
__global__ void k_fc(const float* __restrict__ w0, const float* __restrict__ b0,
                     const float* __restrict__ w1, const float* __restrict__ b1,
                     const float* __restrict__ w2, const float* __restrict__ b2,
                     float* __restrict__ out) {
    __shared__ float sx[400];
    __shared__ float sy0[200];
    __shared__ float sy1[100];
    int b = blockIdx.x, tid = threadIdx.x;
    for (int k = tid; k < 400; k += blockDim.x)
        sx[k] = (k < 200) ? g_emb[b * 200 + k] : g_prot[b * 200 + (k - 200)];
    __syncthreads();
    for (int j = tid; j < 200; j += blockDim.x) {
        float a = b0[j];
        for (int k = 0; k < 400; k++) a += sx[k] * w0[k * 200 + j];
        sy0[j] = fmaxf(a, 0.f);
    }
    __syncthreads();
    for (int j = tid; j < 100; j += blockDim.x) {
        float a = b1[j];
        for (int k = 0; k < 200; k++) a += sy0[k] * w1[k * 100 + j];
        sy1[j] = fmaxf(a, 0.f);
    }
    __syncthreads();
    if (tid == 0) {
        float a = b2[0];
        for (int k = 0; k < 100; k++) a += sy1[k] * w2[k];
        out[b] = a;
    }
}

// ---------------- launch --------------------------------------------------
extern "C" void kernel_launch(void* const* d_in, const int* in_sizes, int n_in,
                              void* d_out, int out_size) {
    const float* fatoms = (const float*)d_in[0];
    const float* fbonds = (const float*)d_in[1];
    const int* agraph = (const int*)d_in[2];
    const int* bgraph = (const int*)d_in[3];
    const int* pseq = (const int*)d_in[4];
    const float* W_i = (const float*)d_in[5];
    const float* W_h = (const float*)d_in[6];
    const float* W_o_w = (const float*)d_in[7];
    const float* W_o_b = (const float*)d_in[8];
    const float* Ep = (const float*)d_in[9];
    const float* c0w = (const float*)d_in[10];
    const float* c0b = (const float*)d_in[11];
    const float* c1w = (const float*)d_in[12];
    const float* c1b = (const float*)d_in[13];
    const float* c2w = (const float*)d_in[14];
    const float* c2b = (const float*)d_in[15];
    const float* f0w = (const float*)d_in[16];
    const float* f0b = (const float*)d_in[17];
    const float* f1w = (const float*)d_in[18];
    const float* f1b = (const float*)d_in[19];
    const float* f2w = (const float*)d_in[20];
    const float* f2b = (const float*)d_in[21];
    float* out = (float*)d_out;

    // conv dynamic smem: (2*CI_TILE*NP + CI_TILE*K*CoT) * 8
    const int smem_c0 = (2 * 25 * 131 + 25 * 3 * 48) * 8;   // 81200
    const int smem_c1 = (2 * 16 * 132 + 16 * 5 * 64) * 8;   // 74752
    const int smem_c2 = (2 * 16 * 133 + 16 * 7 * 40) * 8;   // 69888

    // Resolve REAL device addresses of __device__ globals passed as args.
    static float *p_pv1 = nullptr, *p_pv2 = nullptr, *p_prot = nullptr,
                 *p_nei = nullptr, *p_binput = nullptr, *p_message = nullptr,
                 *p_ain = nullptr, *p_wo = nullptr, *p_atomh = nullptr;
    static cudaStream_t s2 = nullptr;
    static cudaEvent_t evFork = nullptr, evJoin = nullptr;
    static bool init_done = false;
    if (!init_done) {
        cudaGetSymbolAddress((void**)&p_pv1, g_pv1);
        cudaGetSymbolAddress((void**)&p_pv2, g_pv2);
        cudaGetSymbolAddress((void**)&p_prot, g_prot);
        cudaGetSymbolAddress((void**)&p_nei, g_nei);
        cudaGetSymbolAddress((void**)&p_binput, g_binput);
        cudaGetSymbolAddress((void**)&p_message, g_message);
        cudaGetSymbolAddress((void**)&p_ain, g_ain);
        cudaGetSymbolAddress((void**)&p_wo, g_wo);
        cudaGetSymbolAddress((void**)&p_atomh, g_atomh);
        cudaStreamCreateWithFlags(&s2, cudaStreamNonBlocking);
        cudaEventCreateWithFlags(&evFork, cudaEventDisableTiming);
        cudaEventCreateWithFlags(&evJoin, cudaEventDisableTiming);
        cudaFuncSetAttribute((const void*)conv_kernel<50, 96, 3, 25, 48, 192, false, true>,
                             cudaFuncAttributeMaxDynamicSharedMemorySize, smem_c0);
        cudaFuncSetAttribute((const void*)conv_kernel<96, 128, 5, 16, 64, 256, false, false>,
                             cudaFuncAttributeMaxDynamicSharedMemorySize, smem_c1);
        cudaFuncSetAttribute((const void*)conv_kernel<128, 200, 7, 16, 40, 160, true, false>,
                             cudaFuncAttributeMaxDynamicSharedMemorySize, smem_c2);
        init_done = true;
    }

    // ---- fork: MPNN chain runs on s2, conv tower on the main stream ----
    cudaEventRecord(evFork, 0);
    cudaStreamWaitEvent(s2, evFork, 0);

    // MPNN chain (stream s2)
    k_pad_w<<<(KAo * Hc + 255) / 256, 256, 0, s2>>>(W_o_w);
    {
        dim3 g(Mrows / 256, 4);
        int gg = (Mrows * Hc + 255) / 256;
        gemm_kernel<50, 25, 0><<<g, 256, 0, s2>>>(fbonds, W_i, nullptr, p_binput, p_message);
        k_gather<<<gg, 256, 0, s2>>>(bgraph);
        gemm_kernel<200, 25, 1><<<g, 256, 0, s2>>>(p_nei, W_h, nullptr, p_binput, p_message);
        k_gather<<<gg, 256, 0, s2>>>(bgraph);
        gemm_kernel<200, 25, 1><<<g, 256, 0, s2>>>(p_nei, W_h, nullptr, p_binput, p_message);
    }
    k_gather_atoms<<<(Marows * KAo + 255) / 256, 256, 0, s2>>>(agraph, fatoms);
    {
        dim3 g(Marows / 256, 4);
        gemm_kernel<KAo, 24, 2><<<g, 256, 0, s2>>>(p_ain, p_wo, W_o_b, nullptr, p_atomh);
    }
    k_mean<<<Bm, 224, 0, s2>>>();

    // protein tower (main stream)
    k_zero_prot<<<(Bm * Hc + 255) / 256, 256>>>();
    {
        dim3 g(4, 2, Bm);   // 96 = 2 x 48
        conv_kernel<50, 96, 3, 25, 48, 192, false, true><<<g, 192, smem_c0>>>(
            nullptr, pseq, Ep, c0w, c0b, p_pv1, nullptr);
    }
    {
        dim3 g(4, 2, Bm);   // 128 = 2 x 64
        conv_kernel<96, 128, 5, 16, 64, 256, false, false><<<g, 256, smem_c1>>>(
            p_pv1, nullptr, nullptr, c1w, c1b, p_pv2, nullptr);
    }
    {
        dim3 g(4, 5, Bm);   // 200 = 5 x 40
        conv_kernel<128, 200, 7, 16, 40, 160, true, false><<<g, 160, smem_c2>>>(
            p_pv2, nullptr, nullptr, c2w, c2b, nullptr, p_prot);
    }

    // ---- join: fc head needs both g_emb (s2) and g_prot (main) ----
    cudaEventRecord(evJoin, s2);
    cudaStreamWaitEvent(0, evJoin, 0);
    k_fc<<<Bm, 256>>>(f0w, f0b, f1w, f1b, f2w, f2b, out);
}